// round 12
// baseline (speedup 1.0000x reference)
#include <cuda_runtime.h>
#include <cuda_fp16.h>
#include <cstdint>

// ---------------- problem constants ----------------
#define N_NODES 4096
#define B_SZ 16
#define P_SZ 4
#define D_IN 128
#define E_DIM 192
#define D_MODEL 128

#define ADJ_ELEMS (N_NODES * N_NODES)
#define RES_OFF   ((size_t)ADJ_ELEMS)
#define OUTM_OFF  (RES_OFF + (size_t)B_SZ * N_NODES * D_MODEL)
#define M_OFF     (OUTM_OFF + (size_t)B_SZ * N_NODES * D_MODEL)

#define NCHUNK 9
// chunk order j: 0..5 = feat (seg=j%3, k0=(j/3)*64), 6..8 = edge k0=(j-6)*64
// A phases: P0 feat k0 (j0-2), P1 feat k64 (j3-5), P2/3/4 edge (j6/7/8)

// smem layout (bytes). A/B rows padded to 72 halves (144 B) for conflict-free ldmatrix.
#define AST 72
#define ROWB (AST * 2)
#define OFF_AH 0                        // 132 rows * 144 = 19008
#define OFF_AL 19008                    // -> 38016
#define OFF_B0 38016                    // 2 buffers * 18432 -> 74880
#define BBUF_B 18432
#define OFF_RAW 74880                   // 130 rows * 256 B = 33280 -> 108160
#define DYN_SMEM 108160

// prepacked W (fp16, j-order [9][128 n][64 k])
__device__ __half g_Wpk[NCHUNK * 128 * 64];

// ---------------- helpers ----------------
__device__ __forceinline__ uint32_t smem_u32(const void* p) {
    uint32_t a;
    asm("{ .reg .u64 t; cvta.to.shared.u64 t, %1; cvt.u32.u64 %0, t; }" : "=r"(a) : "l"(p));
    return a;
}
__device__ __forceinline__ void ldm_x4(uint32_t* r, uint32_t addr) {
    asm volatile("ldmatrix.sync.aligned.m8n8.x4.shared.b16 {%0,%1,%2,%3}, [%4];"
        : "=r"(r[0]), "=r"(r[1]), "=r"(r[2]), "=r"(r[3]) : "r"(addr));
}
__device__ __forceinline__ void mma_f16(float* c, const uint32_t* a, const uint32_t* b) {
    asm volatile("mma.sync.aligned.m16n8k16.row.col.f32.f16.f16.f32 "
        "{%0,%1,%2,%3}, {%4,%5,%6,%7}, {%8,%9}, {%0,%1,%2,%3};"
        : "+f"(c[0]), "+f"(c[1]), "+f"(c[2]), "+f"(c[3])
        : "r"(a[0]), "r"(a[1]), "r"(a[2]), "r"(a[3]), "r"(b[0]), "r"(b[1]));
}
__device__ __forceinline__ uint32_t f2h2(float x, float y) {
    __half2 h = __floats2half2_rn(x, y);
    return *reinterpret_cast<uint32_t*>(&h);
}
__device__ __forceinline__ void cpa16(uint32_t dst, const void* src) {
    asm volatile("cp.async.ca.shared.global [%0], [%1], 16;" :: "r"(dst), "l"(src));
}
#define CPA_COMMIT() asm volatile("cp.async.commit_group;" ::: "memory")
#define CPA_WAIT1()  asm volatile("cp.async.wait_group 1;" ::: "memory")
#define CPA_WAIT0()  asm volatile("cp.async.wait_group 0;" ::: "memory")

// ---------------- prep: fp16 + transpose + j-order W ----------------
__global__ void prep_w(const float* __restrict__ W) {
    int i = blockIdx.x * blockDim.x + threadIdx.x;
    if (i >= NCHUNK * 128 * 64) return;
    int c = i / 8192;
    int e = i & 8191;
    int n = e >> 6;
    int kk = e & 63;
    int wrow;
    if (c < 6) { int seg = c % 3, k0 = (c / 3) * 64; wrow = (k0 + kk) * 3 + seg; }
    else       { wrow = 384 + (c - 6) * 64 + kk; }
    g_Wpk[i] = __float2half_rn(W[wrow * D_MODEL + n]);
}

// ---------------- mega kernel: even blocks = GEMM, odd = aux ----------------
__global__ __launch_bounds__(256, 2)
void mega_kernel(const float* __restrict__ adj,
                 const float* __restrict__ feat,
                 const float* __restrict__ edge,
                 const float* __restrict__ mask,
                 const float* __restrict__ bias,
                 float* __restrict__ out) {
    const int tid = threadIdx.x;

    if (blockIdx.x & 1) {
        // ---- aux: adj passthrough (streaming, L1-bypass) + m output ----
        int idx = (blockIdx.x >> 1) * 256 + tid;
        const float4* src = (const float4*)adj;
        float4* dst = (float4*)out;
        #pragma unroll 8
        for (int i = idx; i < ADJ_ELEMS / 4; i += 512 * 256)
            __stcs(dst + i, __ldcs(src + i));
        for (int i = idx; i < P_SZ * N_NODES; i += 512 * 256) {
            int n = i & (N_NODES - 1);
            float v = mask[i];
            if (n + 1 < N_NODES) v = fmaxf(v, mask[i + 1]);
            if (n + 2 < N_NODES) v = fmaxf(v, mask[i + 2]);
            out[M_OFF + i] = v;
        }
        return;
    }

    // ---- GEMM block ----
    extern __shared__ char smem[];
    const int g  = blockIdx.x >> 1;
    const int b  = g >> 5;
    const int n0 = (g & 31) << 7;
    const int w    = tid >> 5;
    const int lane = tid & 31;
    const int mb = (w & 3) * 32;     // warp M base
    const int nb = (w >> 2) * 64;    // warp N base

    const uint32_t sb  = smem_u32(smem);
    const uint32_t aHb = sb + OFF_AH, aLb = sb + OFF_AL;
    const uint32_t rawb = sb + OFF_RAW;

    float acc[2][8][4];
    #pragma unroll
    for (int mf = 0; mf < 2; ++mf)
        #pragma unroll
        for (int nf = 0; nf < 8; ++nf)
            #pragma unroll
            for (int q = 0; q < 4; ++q) acc[mf][nf][q] = 0.f;

    // ---- prefetch helpers ----
    auto issue_feat_raw = [&](int k0) {
        const float* base = feat + (size_t)b * N_NODES * D_IN + k0;
        #pragma unroll
        for (int i = 0; i < 9; ++i) {
            int L = tid + (i << 8);
            if (L < 130 * 16) {
                int row = L >> 4, c4 = L & 15;
                int gr = n0 + row;
                uint32_t dst = rawb + L * 16;
                if (gr < N_NODES)
                    cpa16(dst, base + (size_t)gr * D_IN + c4 * 4);
                else
                    *(float4*)(smem + OFF_RAW + L * 16) = make_float4(0.f, 0.f, 0.f, 0.f);
            }
        }
    };
    auto issue_edge_raw = [&](int e) {
        const float* base = edge + (size_t)b * N_NODES * E_DIM + e * 64;
        #pragma unroll
        for (int i = 0; i < 8; ++i) {
            int L = tid + (i << 8);
            int row = L >> 4, c4 = L & 15;
            cpa16(rawb + L * 16, base + (size_t)(n0 + row) * E_DIM + c4 * 4);
        }
    };
    auto issue_B = [&](int c) {
        const __half* src = g_Wpk + (size_t)c * 8192;
        uint32_t bb = sb + OFF_B0 + (uint32_t)(c & 1) * BBUF_B;
        #pragma unroll
        for (int i = 0; i < 4; ++i) {
            int gg = tid + (i << 8);
            uint32_t off = (uint32_t)((gg >> 3) * ROWB + (gg & 7) * 16);
            cpa16(bb + off, src + gg * 8);
        }
    };
    auto convert_A = [&](int nrows) {
        #pragma unroll
        for (int i = 0; i < 9; ++i) {
            int L = tid + (i << 8);
            if (L < nrows * 16) {
                int row = L >> 4, c4 = L & 15;
                float4 v = *(const float4*)(smem + OFF_RAW + L * 16);
                uint32_t hx = f2h2(v.x, v.y);
                uint32_t hz = f2h2(v.z, v.w);
                float lx = v.x - __half2float(__ushort_as_half((unsigned short)(hx & 0xFFFF)));
                float ly = v.y - __half2float(__ushort_as_half((unsigned short)(hx >> 16)));
                float lz = v.z - __half2float(__ushort_as_half((unsigned short)(hz & 0xFFFF)));
                float lw = v.w - __half2float(__ushort_as_half((unsigned short)(hz >> 16)));
                int eo = row * AST + c4 * 4;
                *(uint2*)((__half*)(smem + OFF_AH) + eo) = make_uint2(hx, hz);
                *(uint2*)((__half*)(smem + OFF_AL) + eo) =
                    make_uint2(f2h2(lx, ly), f2h2(lz, lw));
            }
        }
    };

    // pre-loop: C0 = raw P0 (feat k0) + B chunk 0
    issue_feat_raw(0);
    issue_B(0);
    CPA_COMMIT();

    for (int j = 0; j < NCHUNK; ++j) {
        __syncthreads();                       // (a) prior compute done

        if (j == 0 || j == 7 || j == 8) {      // raw for this phase committed last chunk
            CPA_WAIT0();
            __syncthreads();
        }
        const bool newphase = (j == 0 || j == 3 || j >= 6);
        if (newphase) {
            convert_A(j < 6 ? 130 : 128);
            __syncthreads();                   // (b) Ah/Al + raw-stage free
        }
        if (j < 8) {
            if (j == 0) issue_feat_raw(64);
            else if (j == 3) issue_edge_raw(0);
            else if (j == 6) issue_edge_raw(1);
            else if (j == 7) issue_edge_raw(2);
            issue_B(j + 1);
            CPA_COMMIT();
            CPA_WAIT1();                       // B(j) complete; newest group may fly
            __syncthreads();                   // (c)
        }

        // ---- compute chunk j ----
        const uint32_t aoff = (uint32_t)((j < 6 ? (j % 3) : 0) * ROWB);
        const uint32_t bHb = sb + OFF_B0 + (uint32_t)(j & 1) * BBUF_B;

        #pragma unroll
        for (int ks = 0; ks < 4; ++ks) {
            uint32_t ah[2][4], al[2][4];
            #pragma unroll
            for (int mf = 0; mf < 2; ++mf) {
                uint32_t off = aoff + (uint32_t)((mb + mf * 16 + (lane & 15)) * ROWB
                                                 + ks * 32 + (lane >> 4) * 16);
                ldm_x4(ah[mf], aHb + off);
                ldm_x4(al[mf], aLb + off);
            }
            #pragma unroll
            for (int nfp = 0; nfp < 4; ++nfp) {
                uint32_t boff = (uint32_t)((nb + nfp * 16 + ((lane >> 4) & 1) * 8 + (lane & 7)) * ROWB
                                           + ks * 32 + ((lane >> 3) & 1) * 16);
                uint32_t bh4[4];
                ldm_x4(bh4, bHb + boff);
                #pragma unroll
                for (int h = 0; h < 2; ++h) {
                    int nf = nfp * 2 + h;
                    mma_f16(acc[0][nf], ah[0], bh4 + h * 2);
                    mma_f16(acc[1][nf], ah[1], bh4 + h * 2);
                    mma_f16(acc[0][nf], al[0], bh4 + h * 2);
                    mma_f16(acc[1][nf], al[1], bh4 + h * 2);
                }
            }
        }
    }

    // ---- epilogue (registers only; feat re-reads hit L2) ----
    const int p = b & (P_SZ - 1);
    const float inv3 = 1.0f / 3.0f;
    float2 bias2[8];
    #pragma unroll
    for (int nf = 0; nf < 8; ++nf)
        bias2[nf] = *(const float2*)(bias + nb + nf * 8 + (lane & 3) * 2);

    float* res  = out + RES_OFF;
    float* outm = out + OUTM_OFF;

    #pragma unroll
    for (int mf = 0; mf < 2; ++mf) {
        #pragma unroll
        for (int h = 0; h < 2; ++h) {
            int n = n0 + mb + mf * 16 + h * 8 + (lane >> 2);
            float mv = mask[p * N_NODES + n];
            if (n + 1 < N_NODES) mv = fmaxf(mv, mask[p * N_NODES + n + 1]);
            if (n + 2 < N_NODES) mv = fmaxf(mv, mask[p * N_NODES + n + 2]);
            const size_t obase = ((size_t)(b * N_NODES + n)) * D_MODEL;
            const float* f0 = feat + ((size_t)(b * N_NODES + n)) * D_IN;
            #pragma unroll
            for (int nf = 0; nf < 8; ++nf) {
                int col = nb + nf * 8 + (lane & 3) * 2;
                float j0 = 0.f, j1 = 0.f;
                #pragma unroll
                for (int f = 0; f < 3; ++f) {
                    if (n + f < N_NODES) {
                        float2 v = *(const float2*)(f0 + (size_t)f * D_IN + col);
                        j0 += v.x; j1 += v.y;
                    }
                }
                float o0 = fmaxf(acc[mf][nf][h * 2 + 0] + bias2[nf].x, 0.f);
                float o1 = fmaxf(acc[mf][nf][h * 2 + 1] + bias2[nf].y, 0.f);
                *(float2*)(outm + obase + col) = make_float2(mv * o0, mv * o1);
                *(float2*)(res  + obase + col) =
                    make_float2(mv * (o0 + j0 * inv3), mv * (o1 + j1 * inv3));
            }
        }
    }
}

// ---------------- launch ----------------
extern "C" void kernel_launch(void* const* d_in, const int* in_sizes, int n_in,
                              void* d_out, int out_size) {
    const float* adj  = (const float*)d_in[0];
    const float* feat = (const float*)d_in[1];
    const float* edge = (const float*)d_in[2];
    const float* mask = (const float*)d_in[3];
    const float* W    = (const float*)d_in[4];
    const float* bias = (const float*)d_in[5];
    float* out = (float*)d_out;

    cudaFuncSetAttribute(mega_kernel, cudaFuncAttributeMaxDynamicSharedMemorySize, DYN_SMEM);

    prep_w<<<(NCHUNK * 128 * 64 + 255) / 256, 256>>>(W);
    mega_kernel<<<1024, 256, DYN_SMEM>>>(adj, feat, edge, mask, bias, out);
}

// round 13
// speedup vs baseline: 1.2495x; 1.2495x over previous
#include <cuda_runtime.h>
#include <cuda_fp16.h>
#include <cstdint>

// ---------------- problem constants ----------------
#define N_NODES 4096
#define B_SZ 16
#define P_SZ 4
#define D_IN 128
#define E_DIM 192
#define D_MODEL 128

#define ADJ_ELEMS (N_NODES * N_NODES)
#define RES_OFF   ((size_t)ADJ_ELEMS)
#define OUTM_OFF  (RES_OFF + (size_t)B_SZ * N_NODES * D_MODEL)
#define M_OFF     (OUTM_OFF + (size_t)B_SZ * N_NODES * D_MODEL)

#define NCHUNK 9
// chunk order j: 0..5 = feat (seg=j%3, k0=(j/3)*64), 6..8 = edge k0=(j-6)*64
// A phases: P0 feat k0 (j0-2), P1 feat k64 (j3-5), P2/3/4 edge (j6/7/8)

// smem layout (bytes). A/B rows padded to 72 halves (144 B) for conflict-free ldmatrix.
#define AST 72
#define ROWB (AST * 2)
#define OFF_AH 0                        // 132 rows * 144 = 19008
#define OFF_AL 19008                    // -> 38016
#define OFF_B0 38016                    // 2 buffers * 18432 -> 74880
#define BBUF_B 18432
#define OFF_RAW 74880                   // 130 rows * 256 B = 33280 -> 108160
#define DYN_SMEM 108160

// prepacked W (fp16, j-order [9][128 n][64 k])
__device__ __half g_Wpk[NCHUNK * 128 * 64];

// ---------------- helpers ----------------
__device__ __forceinline__ uint32_t smem_u32(const void* p) {
    uint32_t a;
    asm("{ .reg .u64 t; cvta.to.shared.u64 t, %1; cvt.u32.u64 %0, t; }" : "=r"(a) : "l"(p));
    return a;
}
__device__ __forceinline__ void ldm_x4(uint32_t* r, uint32_t addr) {
    asm volatile("ldmatrix.sync.aligned.m8n8.x4.shared.b16 {%0,%1,%2,%3}, [%4];"
        : "=r"(r[0]), "=r"(r[1]), "=r"(r[2]), "=r"(r[3]) : "r"(addr));
}
__device__ __forceinline__ void mma_f16(float* c, const uint32_t* a, const uint32_t* b) {
    asm volatile("mma.sync.aligned.m16n8k16.row.col.f32.f16.f16.f32 "
        "{%0,%1,%2,%3}, {%4,%5,%6,%7}, {%8,%9}, {%0,%1,%2,%3};"
        : "+f"(c[0]), "+f"(c[1]), "+f"(c[2]), "+f"(c[3])
        : "r"(a[0]), "r"(a[1]), "r"(a[2]), "r"(a[3]), "r"(b[0]), "r"(b[1]));
}
__device__ __forceinline__ uint32_t f2h2(float x, float y) {
    __half2 h = __floats2half2_rn(x, y);
    return *reinterpret_cast<uint32_t*>(&h);
}
__device__ __forceinline__ void cpa16(uint32_t dst, const void* src) {
    asm volatile("cp.async.ca.shared.global [%0], [%1], 16;" :: "r"(dst), "l"(src));
}
#define CPA_COMMIT() asm volatile("cp.async.commit_group;" ::: "memory")
#define CPA_WAIT1()  asm volatile("cp.async.wait_group 1;" ::: "memory")
#define CPA_WAIT0()  asm volatile("cp.async.wait_group 0;" ::: "memory")

// ---------------- prep: fp16 + transpose + j-order W ----------------
__global__ void prep_w(const float* __restrict__ W) {
    int i = blockIdx.x * blockDim.x + threadIdx.x;
    if (i >= NCHUNK * 128 * 64) return;
    int c = i / 8192;
    int e = i & 8191;
    int n = e >> 6;
    int kk = e & 63;
    int wrow;
    if (c < 6) { int seg = c % 3, k0 = (c / 3) * 64; wrow = (k0 + kk) * 3 + seg; }
    else       { wrow = 384 + (c - 6) * 64 + kk; }
    g_Wpk[i] = __float2half_rn(W[wrow * D_MODEL + n]);
}

// ---------------- mega kernel: blocks 0..511 GEMM, 512..1023 aux ----------------
__global__ __launch_bounds__(256, 2)
void mega_kernel(const float* __restrict__ adj,
                 const float* __restrict__ feat,
                 const float* __restrict__ edge,
                 const float* __restrict__ mask,
                 const float* __restrict__ bias,
                 float* __restrict__ out) {
    const int tid = threadIdx.x;

    if (blockIdx.x >= 512) {
        // ---- aux: adj passthrough + m output ----
        int idx = (blockIdx.x - 512) * 256 + tid;
        const float4* src = (const float4*)adj;
        float4* dst = (float4*)out;
        #pragma unroll 8
        for (int i = idx; i < ADJ_ELEMS / 4; i += 512 * 256) dst[i] = src[i];
        for (int i = idx; i < P_SZ * N_NODES; i += 512 * 256) {
            int n = i & (N_NODES - 1);
            float v = mask[i];
            if (n + 1 < N_NODES) v = fmaxf(v, mask[i + 1]);
            if (n + 2 < N_NODES) v = fmaxf(v, mask[i + 2]);
            out[M_OFF + i] = v;
        }
        return;
    }

    // ---- GEMM block ----
    extern __shared__ char smem[];
    const int g  = blockIdx.x;
    const int b  = g >> 5;
    const int n0 = (g & 31) << 7;
    const int w    = tid >> 5;
    const int lane = tid & 31;
    const int mb = (w & 3) * 32;     // warp M base
    const int nb = (w >> 2) * 64;    // warp N base

    const uint32_t sb  = smem_u32(smem);
    const uint32_t aHb = sb + OFF_AH, aLb = sb + OFF_AL;
    const uint32_t rawb = sb + OFF_RAW;

    float acc[2][8][4];
    #pragma unroll
    for (int mf = 0; mf < 2; ++mf)
        #pragma unroll
        for (int nf = 0; nf < 8; ++nf)
            #pragma unroll
            for (int q = 0; q < 4; ++q) acc[mf][nf][q] = 0.f;

    // ---- prefetch helpers ----
    auto issue_feat_raw = [&](int k0) {
        const float* base = feat + (size_t)b * N_NODES * D_IN + k0;
        #pragma unroll
        for (int i = 0; i < 9; ++i) {
            int L = tid + (i << 8);
            if (L < 130 * 16) {
                int row = L >> 4, c4 = L & 15;
                int gr = n0 + row;
                uint32_t dst = rawb + L * 16;
                if (gr < N_NODES)
                    cpa16(dst, base + (size_t)gr * D_IN + c4 * 4);
                else
                    *(float4*)(smem + OFF_RAW + L * 16) = make_float4(0.f, 0.f, 0.f, 0.f);
            }
        }
    };
    auto issue_edge_raw = [&](int e) {
        const float* base = edge + (size_t)b * N_NODES * E_DIM + e * 64;
        #pragma unroll
        for (int i = 0; i < 8; ++i) {
            int L = tid + (i << 8);
            int row = L >> 4, c4 = L & 15;
            cpa16(rawb + L * 16, base + (size_t)(n0 + row) * E_DIM + c4 * 4);
        }
    };
    auto issue_B = [&](int c) {
        const __half* src = g_Wpk + (size_t)c * 8192;
        uint32_t bb = sb + OFF_B0 + (uint32_t)(c & 1) * BBUF_B;
        #pragma unroll
        for (int i = 0; i < 4; ++i) {
            int gg = tid + (i << 8);
            uint32_t off = (uint32_t)((gg >> 3) * ROWB + (gg & 7) * 16);
            cpa16(bb + off, src + gg * 8);
        }
    };
    auto convert_A = [&](int nrows) {
        #pragma unroll
        for (int i = 0; i < 9; ++i) {
            int L = tid + (i << 8);
            if (L < nrows * 16) {
                int row = L >> 4, c4 = L & 15;
                float4 v = *(const float4*)(smem + OFF_RAW + L * 16);
                uint32_t hx = f2h2(v.x, v.y);
                uint32_t hz = f2h2(v.z, v.w);
                float lx = v.x - __half2float(__ushort_as_half((unsigned short)(hx & 0xFFFF)));
                float ly = v.y - __half2float(__ushort_as_half((unsigned short)(hx >> 16)));
                float lz = v.z - __half2float(__ushort_as_half((unsigned short)(hz & 0xFFFF)));
                float lw = v.w - __half2float(__ushort_as_half((unsigned short)(hz >> 16)));
                int eo = row * AST + c4 * 4;
                *(uint2*)((__half*)(smem + OFF_AH) + eo) = make_uint2(hx, hz);
                *(uint2*)((__half*)(smem + OFF_AL) + eo) =
                    make_uint2(f2h2(lx, ly), f2h2(lz, lw));
            }
        }
    };

    // pre-loop: C0 = raw P0 (feat k0) + B chunk 0
    issue_feat_raw(0);
    issue_B(0);
    CPA_COMMIT();

    for (int j = 0; j < NCHUNK; ++j) {
        __syncthreads();                       // (a) prior compute done

        if (j == 0 || j == 7 || j == 8) {      // raw for this phase committed last chunk
            CPA_WAIT0();
            __syncthreads();
        }
        const bool newphase = (j == 0 || j == 3 || j >= 6);
        if (newphase) {
            convert_A(j < 6 ? 130 : 128);
            __syncthreads();                   // (b) Ah/Al + raw-stage free
        }
        if (j < 8) {
            if (j == 0) issue_feat_raw(64);
            else if (j == 3) issue_edge_raw(0);
            else if (j == 6) issue_edge_raw(1);
            else if (j == 7) issue_edge_raw(2);
            issue_B(j + 1);
            CPA_COMMIT();
            CPA_WAIT1();                       // B(j) complete; newest group may fly
            __syncthreads();                   // (c)
        }

        // ---- compute chunk j ----
        const uint32_t aoff = (uint32_t)((j < 6 ? (j % 3) : 0) * ROWB);
        const uint32_t bHb = sb + OFF_B0 + (uint32_t)(j & 1) * BBUF_B;

        #pragma unroll
        for (int ks = 0; ks < 4; ++ks) {
            uint32_t ah[2][4], al[2][4];
            #pragma unroll
            for (int mf = 0; mf < 2; ++mf) {
                uint32_t off = aoff + (uint32_t)((mb + mf * 16 + (lane & 15)) * ROWB
                                                 + ks * 32 + (lane >> 4) * 16);
                ldm_x4(ah[mf], aHb + off);
                ldm_x4(al[mf], aLb + off);
            }
            #pragma unroll
            for (int nfp = 0; nfp < 4; ++nfp) {
                uint32_t boff = (uint32_t)((nb + nfp * 16 + ((lane >> 4) & 1) * 8 + (lane & 7)) * ROWB
                                           + ks * 32 + ((lane >> 3) & 1) * 16);
                uint32_t bh4[4];
                ldm_x4(bh4, bHb + boff);
                // hi pass: 4 independent MMAs (acc reuse distance 4)
                #pragma unroll
                for (int h = 0; h < 2; ++h) {
                    int nf = nfp * 2 + h;
                    mma_f16(acc[0][nf], ah[0], bh4 + h * 2);
                    mma_f16(acc[1][nf], ah[1], bh4 + h * 2);
                }
                // lo pass: 4 independent MMAs (same B frags, distance 4)
                #pragma unroll
                for (int h = 0; h < 2; ++h) {
                    int nf = nfp * 2 + h;
                    mma_f16(acc[0][nf], al[0], bh4 + h * 2);
                    mma_f16(acc[1][nf], al[1], bh4 + h * 2);
                }
            }
        }
    }

    // ---- epilogue (registers only; feat re-reads hit L2) ----
    const int p = b & (P_SZ - 1);
    const float inv3 = 1.0f / 3.0f;
    float2 bias2[8];
    #pragma unroll
    for (int nf = 0; nf < 8; ++nf)
        bias2[nf] = *(const float2*)(bias + nb + nf * 8 + (lane & 3) * 2);

    float* res  = out + RES_OFF;
    float* outm = out + OUTM_OFF;

    #pragma unroll
    for (int mf = 0; mf < 2; ++mf) {
        #pragma unroll
        for (int h = 0; h < 2; ++h) {
            int n = n0 + mb + mf * 16 + h * 8 + (lane >> 2);
            float mv = mask[p * N_NODES + n];
            if (n + 1 < N_NODES) mv = fmaxf(mv, mask[p * N_NODES + n + 1]);
            if (n + 2 < N_NODES) mv = fmaxf(mv, mask[p * N_NODES + n + 2]);
            const size_t obase = ((size_t)(b * N_NODES + n)) * D_MODEL;
            const float* f0 = feat + ((size_t)(b * N_NODES + n)) * D_IN;
            #pragma unroll
            for (int nf = 0; nf < 8; ++nf) {
                int col = nb + nf * 8 + (lane & 3) * 2;
                float j0 = 0.f, j1 = 0.f;
                #pragma unroll
                for (int f = 0; f < 3; ++f) {
                    if (n + f < N_NODES) {
                        float2 v = *(const float2*)(f0 + (size_t)f * D_IN + col);
                        j0 += v.x; j1 += v.y;
                    }
                }
                float o0 = fmaxf(acc[mf][nf][h * 2 + 0] + bias2[nf].x, 0.f);
                float o1 = fmaxf(acc[mf][nf][h * 2 + 1] + bias2[nf].y, 0.f);
                *(float2*)(outm + obase + col) = make_float2(mv * o0, mv * o1);
                *(float2*)(res  + obase + col) =
                    make_float2(mv * (o0 + j0 * inv3), mv * (o1 + j1 * inv3));
            }
        }
    }
}

// ---------------- launch ----------------
extern "C" void kernel_launch(void* const* d_in, const int* in_sizes, int n_in,
                              void* d_out, int out_size) {
    const float* adj  = (const float*)d_in[0];
    const float* feat = (const float*)d_in[1];
    const float* edge = (const float*)d_in[2];
    const float* mask = (const float*)d_in[3];
    const float* W    = (const float*)d_in[4];
    const float* bias = (const float*)d_in[5];
    float* out = (float*)d_out;

    cudaFuncSetAttribute(mega_kernel, cudaFuncAttributeMaxDynamicSharedMemorySize, DYN_SMEM);

    prep_w<<<(NCHUNK * 128 * 64 + 255) / 256, 256>>>(W);
    mega_kernel<<<1024, 256, DYN_SMEM>>>(adj, feat, edge, mask, bias, out);
}

// round 14
// speedup vs baseline: 1.7395x; 1.3921x over previous
#include <cuda_runtime.h>
#include <cuda_fp16.h>
#include <cstdint>

// ---------------- problem constants ----------------
#define N_NODES 4096
#define B_SZ 16
#define P_SZ 4
#define D_IN 128
#define E_DIM 192
#define D_MODEL 128

#define ADJ_ELEMS (N_NODES * N_NODES)
#define RES_OFF   ((size_t)ADJ_ELEMS)
#define OUTM_OFF  (RES_OFF + (size_t)B_SZ * N_NODES * D_MODEL)
#define M_OFF     (OUTM_OFF + (size_t)B_SZ * N_NODES * D_MODEL)

#define NCHUNK 9
// chunk order j: 0..5 = feat (seg=j%3, k0=(j/3)*64), 6..8 = edge k0=(j-6)*64
// A phases: P0 feat k0 (j0-2), P1 feat k64 (j3-5), P2/3/4 edge (j6/7/8)

// smem layout (bytes). A/B rows padded to 72 halves (144 B) for conflict-free ldmatrix.
#define AST 72
#define ROWB (AST * 2)
#define OFF_AH 0                        // 132 rows * 144 = 19008
#define OFF_B0 19008                    // 2 buffers * 18432 -> 55872
#define BBUF_B 18432
#define OFF_RAW 55872                   // 130 rows * 256 B = 33280 -> 89152
#define DYN_SMEM 89152

// prepacked W (fp16, j-order [9][128 n][64 k])
__device__ __half g_Wpk[NCHUNK * 128 * 64];

// ---------------- helpers ----------------
__device__ __forceinline__ uint32_t smem_u32(const void* p) {
    uint32_t a;
    asm("{ .reg .u64 t; cvta.to.shared.u64 t, %1; cvt.u32.u64 %0, t; }" : "=r"(a) : "l"(p));
    return a;
}
__device__ __forceinline__ void ldm_x4(uint32_t* r, uint32_t addr) {
    asm volatile("ldmatrix.sync.aligned.m8n8.x4.shared.b16 {%0,%1,%2,%3}, [%4];"
        : "=r"(r[0]), "=r"(r[1]), "=r"(r[2]), "=r"(r[3]) : "r"(addr));
}
__device__ __forceinline__ void mma_f16(float* c, const uint32_t* a, const uint32_t* b) {
    asm volatile("mma.sync.aligned.m16n8k16.row.col.f32.f16.f16.f32 "
        "{%0,%1,%2,%3}, {%4,%5,%6,%7}, {%8,%9}, {%0,%1,%2,%3};"
        : "+f"(c[0]), "+f"(c[1]), "+f"(c[2]), "+f"(c[3])
        : "r"(a[0]), "r"(a[1]), "r"(a[2]), "r"(a[3]), "r"(b[0]), "r"(b[1]));
}
__device__ __forceinline__ uint32_t f2h2(float x, float y) {
    __half2 h = __floats2half2_rn(x, y);
    return *reinterpret_cast<uint32_t*>(&h);
}
__device__ __forceinline__ void cpa16(uint32_t dst, const void* src) {
    asm volatile("cp.async.ca.shared.global [%0], [%1], 16;" :: "r"(dst), "l"(src));
}
#define CPA_COMMIT() asm volatile("cp.async.commit_group;" ::: "memory")
#define CPA_WAIT1()  asm volatile("cp.async.wait_group 1;" ::: "memory")
#define CPA_WAIT0()  asm volatile("cp.async.wait_group 0;" ::: "memory")

// ---------------- prep: fp16 + transpose + j-order W ----------------
__global__ void prep_w(const float* __restrict__ W) {
    int i = blockIdx.x * blockDim.x + threadIdx.x;
    if (i >= NCHUNK * 128 * 64) return;
    int c = i / 8192;
    int e = i & 8191;
    int n = e >> 6;
    int kk = e & 63;
    int wrow;
    if (c < 6) { int seg = c % 3, k0 = (c / 3) * 64; wrow = (k0 + kk) * 3 + seg; }
    else       { wrow = 384 + (c - 6) * 64 + kk; }
    g_Wpk[i] = __float2half_rn(W[wrow * D_MODEL + n]);
}

// ---------------- mega kernel: blocks 0..511 GEMM, 512..1023 aux ----------------
__global__ __launch_bounds__(256, 2)
void mega_kernel(const float* __restrict__ adj,
                 const float* __restrict__ feat,
                 const float* __restrict__ edge,
                 const float* __restrict__ mask,
                 const float* __restrict__ bias,
                 float* __restrict__ out) {
    const int tid = threadIdx.x;

    if (blockIdx.x >= 512) {
        // ---- aux: adj passthrough + m output ----
        int idx = (blockIdx.x - 512) * 256 + tid;
        const float4* src = (const float4*)adj;
        float4* dst = (float4*)out;
        #pragma unroll 8
        for (int i = idx; i < ADJ_ELEMS / 4; i += 512 * 256) dst[i] = src[i];
        for (int i = idx; i < P_SZ * N_NODES; i += 512 * 256) {
            int n = i & (N_NODES - 1);
            float v = mask[i];
            if (n + 1 < N_NODES) v = fmaxf(v, mask[i + 1]);
            if (n + 2 < N_NODES) v = fmaxf(v, mask[i + 2]);
            out[M_OFF + i] = v;
        }
        return;
    }

    // ---- GEMM block ----
    extern __shared__ char smem[];
    const int g  = blockIdx.x;
    const int b  = g >> 5;
    const int n0 = (g & 31) << 7;
    const int w    = tid >> 5;
    const int lane = tid & 31;
    const int mb = (w & 3) * 32;     // warp M base
    const int nb = (w >> 2) * 64;    // warp N base

    const uint32_t sb  = smem_u32(smem);
    const uint32_t aHb = sb + OFF_AH;
    const uint32_t rawb = sb + OFF_RAW;

    float acc[2][8][4];
    #pragma unroll
    for (int mf = 0; mf < 2; ++mf)
        #pragma unroll
        for (int nf = 0; nf < 8; ++nf)
            #pragma unroll
            for (int q = 0; q < 4; ++q) acc[mf][nf][q] = 0.f;

    // ---- prefetch helpers ----
    auto issue_feat_raw = [&](int k0) {
        const float* base = feat + (size_t)b * N_NODES * D_IN + k0;
        #pragma unroll
        for (int i = 0; i < 9; ++i) {
            int L = tid + (i << 8);
            if (L < 130 * 16) {
                int row = L >> 4, c4 = L & 15;
                int gr = n0 + row;
                uint32_t dst = rawb + L * 16;
                if (gr < N_NODES)
                    cpa16(dst, base + (size_t)gr * D_IN + c4 * 4);
                else
                    *(float4*)(smem + OFF_RAW + L * 16) = make_float4(0.f, 0.f, 0.f, 0.f);
            }
        }
    };
    auto issue_edge_raw = [&](int e) {
        const float* base = edge + (size_t)b * N_NODES * E_DIM + e * 64;
        #pragma unroll
        for (int i = 0; i < 8; ++i) {
            int L = tid + (i << 8);
            int row = L >> 4, c4 = L & 15;
            cpa16(rawb + L * 16, base + (size_t)(n0 + row) * E_DIM + c4 * 4);
        }
    };
    auto issue_B = [&](int c) {
        const __half* src = g_Wpk + (size_t)c * 8192;
        uint32_t bb = sb + OFF_B0 + (uint32_t)(c & 1) * BBUF_B;
        #pragma unroll
        for (int i = 0; i < 4; ++i) {
            int gg = tid + (i << 8);
            uint32_t off = (uint32_t)((gg >> 3) * ROWB + (gg & 7) * 16);
            cpa16(bb + off, src + gg * 8);
        }
    };
    auto convert_A = [&](int nrows) {
        #pragma unroll
        for (int i = 0; i < 9; ++i) {
            int L = tid + (i << 8);
            if (L < nrows * 16) {
                int row = L >> 4, c4 = L & 15;
                float4 v = *(const float4*)(smem + OFF_RAW + L * 16);
                int eo = row * AST + c4 * 4;
                *(uint2*)((__half*)(smem + OFF_AH) + eo) =
                    make_uint2(f2h2(v.x, v.y), f2h2(v.z, v.w));
            }
        }
    };

    // pre-loop: C0 = raw P0 (feat k0) + B chunk 0
    issue_feat_raw(0);
    issue_B(0);
    CPA_COMMIT();

    for (int j = 0; j < NCHUNK; ++j) {
        __syncthreads();                       // (a) prior compute done

        if (j == 0 || j == 7 || j == 8) {      // raw for this phase committed last chunk
            CPA_WAIT0();
            __syncthreads();
        }
        const bool newphase = (j == 0 || j == 3 || j >= 6);
        if (newphase) {
            convert_A(j < 6 ? 130 : 128);
            __syncthreads();                   // (b) Ah + raw-stage free
        }
        if (j < 8) {
            if (j == 0) issue_feat_raw(64);
            else if (j == 3) issue_edge_raw(0);
            else if (j == 6) issue_edge_raw(1);
            else if (j == 7) issue_edge_raw(2);
            issue_B(j + 1);
            CPA_COMMIT();
            CPA_WAIT1();                       // B(j) complete; newest group may fly
            __syncthreads();                   // (c)
        }

        // ---- compute chunk j ----
        const uint32_t aoff = (uint32_t)((j < 6 ? (j % 3) : 0) * ROWB);
        const uint32_t bHb = sb + OFF_B0 + (uint32_t)(j & 1) * BBUF_B;

        #pragma unroll
        for (int ks = 0; ks < 4; ++ks) {
            uint32_t ah[2][4];
            #pragma unroll
            for (int mf = 0; mf < 2; ++mf) {
                uint32_t off = aoff + (uint32_t)((mb + mf * 16 + (lane & 15)) * ROWB
                                                 + ks * 32 + (lane >> 4) * 16);
                ldm_x4(ah[mf], aHb + off);
            }
            #pragma unroll
            for (int nfp = 0; nfp < 4; ++nfp) {
                uint32_t boff = (uint32_t)((nb + nfp * 16 + ((lane >> 4) & 1) * 8 + (lane & 7)) * ROWB
                                           + ks * 32 + ((lane >> 3) & 1) * 16);
                uint32_t bh4[4];
                ldm_x4(bh4, bHb + boff);
                // 4 independent MMAs per fragment group
                #pragma unroll
                for (int h = 0; h < 2; ++h) {
                    int nf = nfp * 2 + h;
                    mma_f16(acc[0][nf], ah[0], bh4 + h * 2);
                    mma_f16(acc[1][nf], ah[1], bh4 + h * 2);
                }
            }
        }
    }

    // ---- epilogue (registers only; feat re-reads hit L2) ----
    const int p = b & (P_SZ - 1);
    const float inv3 = 1.0f / 3.0f;
    float2 bias2[8];
    #pragma unroll
    for (int nf = 0; nf < 8; ++nf)
        bias2[nf] = *(const float2*)(bias + nb + nf * 8 + (lane & 3) * 2);

    float* res  = out + RES_OFF;
    float* outm = out + OUTM_OFF;

    #pragma unroll
    for (int mf = 0; mf < 2; ++mf) {
        #pragma unroll
        for (int h = 0; h < 2; ++h) {
            int n = n0 + mb + mf * 16 + h * 8 + (lane >> 2);
            float mv = mask[p * N_NODES + n];
            if (n + 1 < N_NODES) mv = fmaxf(mv, mask[p * N_NODES + n + 1]);
            if (n + 2 < N_NODES) mv = fmaxf(mv, mask[p * N_NODES + n + 2]);
            const size_t obase = ((size_t)(b * N_NODES + n)) * D_MODEL;
            const float* f0 = feat + ((size_t)(b * N_NODES + n)) * D_IN;
            #pragma unroll
            for (int nf = 0; nf < 8; ++nf) {
                int col = nb + nf * 8 + (lane & 3) * 2;
                float j0 = 0.f, j1 = 0.f;
                #pragma unroll
                for (int f = 0; f < 3; ++f) {
                    if (n + f < N_NODES) {
                        float2 v = *(const float2*)(f0 + (size_t)f * D_IN + col);
                        j0 += v.x; j1 += v.y;
                    }
                }
                float o0 = fmaxf(acc[mf][nf][h * 2 + 0] + bias2[nf].x, 0.f);
                float o1 = fmaxf(acc[mf][nf][h * 2 + 1] + bias2[nf].y, 0.f);
                *(float2*)(outm + obase + col) = make_float2(mv * o0, mv * o1);
                *(float2*)(res  + obase + col) =
                    make_float2(mv * (o0 + j0 * inv3), mv * (o1 + j1 * inv3));
            }
        }
    }
}

// ---------------- launch ----------------
extern "C" void kernel_launch(void* const* d_in, const int* in_sizes, int n_in,
                              void* d_out, int out_size) {
    const float* adj  = (const float*)d_in[0];
    const float* feat = (const float*)d_in[1];
    const float* edge = (const float*)d_in[2];
    const float* mask = (const float*)d_in[3];
    const float* W    = (const float*)d_in[4];
    const float* bias = (const float*)d_in[5];
    float* out = (float*)d_out;

    cudaFuncSetAttribute(mega_kernel, cudaFuncAttributeMaxDynamicSharedMemorySize, DYN_SMEM);

    prep_w<<<(NCHUNK * 128 * 64 + 255) / 256, 256>>>(W);
    mega_kernel<<<1024, 256, DYN_SMEM>>>(adj, feat, edge, mask, bias, out);
}